// round 15
// baseline (speedup 1.0000x reference)
#include <cuda_runtime.h>
#include <math.h>
#include <stdint.h>

#define HW   4096
#define IMW  64
#define IMH  64
#define WSZ  (144 * 288)   // every tf32 weight matrix has 41472 elements

// ---------------- scratch (device globals; zero-initialized, no allocs) ----------------
__device__ __align__(16) float g_w1t[436 * 64];
__device__ __align__(16) float g_w6t[64 * 432];
__device__ __align__(16) float g_wr[6 * WSZ];   // tf32-pre-rounded: wq,wk,wv,wp,wm1,wm2
__device__ __align__(16) float g_buf0[64 * HW];
__device__ __align__(16) float g_buf1[64 * HW];
__device__ __align__(16) float g_off[432 * HW];
// padded head layout: [pix][12 heads][32 ch] (24 real + 8 zero pad)
__device__ __align__(16) float g_qp[HW * 384];
__device__ __align__(16) float g_kp[2 * HW * 384];
__device__ __align__(16) float g_vp[2 * HW * 384];
__device__ __align__(16) float g_attnout[HW * 384];
__device__ __align__(16) float g_obuf[HW * 144];
__device__ __align__(16) float g_hbuf[HW * 288];

__device__ __forceinline__ unsigned cvt_tf32(float x) {
    unsigned r;
    asm("cvt.rna.tf32.f32 %0, %1;" : "=r"(r) : "f"(x));
    return r;
}

// ---------------- prep: weight transposes + tf32 pre-rounding (one launch) ----------------
__global__ void prep_weights_kernel(const float* __restrict__ w1,
                                    const float* __restrict__ w6,
                                    const float* __restrict__ wq,
                                    const float* __restrict__ wk,
                                    const float* __restrict__ wv,
                                    const float* __restrict__ wp,
                                    const float* __restrict__ wm1,
                                    const float* __restrict__ wm2)
{
    int idx = blockIdx.x * 256 + threadIdx.x;
    if (idx < 436 * 64) {
        int o = idx / 436, i = idx - o * 436;
        g_w1t[i * 64 + o] = w1[idx];
        return;
    }
    idx -= 436 * 64;
    if (idx < 432 * 64) {
        int o = idx / 64, i = idx - o * 64;
        g_w6t[i * 432 + o] = w6[idx];
        return;
    }
    idx -= 432 * 64;
    if (idx < 6 * WSZ) {
        int which = idx / WSZ, r = idx - which * WSZ;
        const float* src;
        switch (which) {
            case 0: src = wq;  break;
            case 1: src = wk;  break;
            case 2: src = wv;  break;
            case 3: src = wp;  break;
            case 4: src = wm1; break;
            default: src = wm2; break;
        }
        g_wr[idx] = __uint_as_float(cvt_tf32(src[r]));
    }
}

// ---------------- cp.async helpers ----------------
__device__ __forceinline__ void cp_async4(uint32_t dst, const void* src, bool p) {
    int sz = p ? 4 : 0;
    asm volatile("cp.async.ca.shared.global [%0], [%1], 4, %2;\n"
                 :: "r"(dst), "l"(src), "r"(sz));
}
__device__ __forceinline__ void cp_commit() {
    asm volatile("cp.async.commit_group;\n");
}
__device__ __forceinline__ void cp_wait1() {
    asm volatile("cp.async.wait_group 1;\n");
}

// ==================== fp32 SGEMM (offset path only) ====================
template<int BM, int BN, int BK, int AMODE, int ACT, int OMODE>
__global__ void gemm_kernel(const float* __restrict__ A, const float* __restrict__ Wm,
                            const float* __restrict__ bias, float* __restrict__ out,
                            const float* __restrict__ extra,
                            const float* __restrict__ A2, const float* __restrict__ A3,
                            const float* __restrict__ A4, const float* __restrict__ A5,
                            int K, int N)
{
    constexpr int TH = BM * BN / 16;
    constexpr int TN = BN / 4;
    constexpr int LA = (BK * BM + TH - 1) / TH;
    constexpr int LW = (BK * BN + TH - 1) / TH;
    __shared__ __align__(16) float sA[BK][BM];
    __shared__ __align__(16) float sW[BK][BN];
    int tid = threadIdx.x;
    int tn = tid % TN, tm = tid / TN;
    int pix0 = blockIdx.x * BM;
    int n0 = blockIdx.y * BN;

    float acc[4][4];
#pragma unroll
    for (int i = 0; i < 4; i++)
#pragma unroll
        for (int j = 0; j < 4; j++) acc[i][j] = 0.f;

    float ra[LA], rw[LW];
    int ktiles = (K + BK - 1) / BK;

    auto loadA = [&](int kt) {
#pragma unroll
        for (int t = 0; t < LA; t++) {
            int idx = tid + t * TH;
            float v = 0.f;
            if (LA * TH == BK * BM || idx < BK * BM) {
                int kk = idx / BM, m = idx % BM;
                int i = kt * BK + kk;
                if (i < K) {
                    int pix = pix0 + m;
                    if (AMODE == 0) v = A[(size_t)i * HW + pix];
                    else {
                        if (i < 144)      v = A [(size_t)i * HW + pix];
                        else if (i < 288) v = A2[(size_t)(i - 144) * HW + pix];
                        else if (i < 432) v = A3[(size_t)(i - 288) * HW + pix];
                        else if (i < 434) v = A4[(size_t)(i - 432) * HW + pix];
                        else              v = A5[(size_t)(i - 434) * HW + pix];
                    }
                }
            }
            ra[t] = v;
        }
    };
    auto loadW = [&](int kt) {
#pragma unroll
        for (int t = 0; t < LW; t++) {
            int idx = tid + t * TH;
            float v = 0.f;
            if (LW * TH == BK * BN || idx < BK * BN) {
                int kk = idx / BN, n = idx - kk * BN;
                int i = kt * BK + kk;
                if (i < K) v = Wm[(size_t)i * N + n0 + n];
            }
            rw[t] = v;
        }
    };

    loadA(0); loadW(0);
    for (int kt = 0; kt < ktiles; kt++) {
#pragma unroll
        for (int t = 0; t < LA; t++) {
            int idx = tid + t * TH;
            if (LA * TH == BK * BM || idx < BK * BM) sA[idx / BM][idx % BM] = ra[t];
        }
#pragma unroll
        for (int t = 0; t < LW; t++) {
            int idx = tid + t * TH;
            if (LW * TH == BK * BN || idx < BK * BN) sW[idx / BN][idx - (idx / BN) * BN] = rw[t];
        }
        __syncthreads();
        if (kt + 1 < ktiles) { loadA(kt + 1); loadW(kt + 1); }
#pragma unroll
        for (int kk = 0; kk < BK; kk++) {
            float4 a4 = *(const float4*)&sA[kk][tm * 4];
            float4 w4 = *(const float4*)&sW[kk][tn * 4];
            float av[4] = {a4.x, a4.y, a4.z, a4.w};
            float wv[4] = {w4.x, w4.y, w4.z, w4.w};
#pragma unroll
            for (int i2 = 0; i2 < 4; i2++)
#pragma unroll
                for (int j = 0; j < 4; j++)
                    acc[i2][j] = fmaf(av[i2], wv[j], acc[i2][j]);
        }
        __syncthreads();
    }

#pragma unroll
    for (int mi = 0; mi < 4; mi++) {
        int m = pix0 + tm * 4 + mi;
        float vals[4];
#pragma unroll
        for (int ni = 0; ni < 4; ni++) {
            int n = n0 + tn * 4 + ni;
            float v = acc[mi][ni] + bias[n];
            if (ACT == 1) {
                v = v >= 0.f ? v : 0.1f * v;
            } else if (ACT == 3) {
                v = 10.f * tanhf(v);
                v += (n & 1) ? extra[m] : extra[HW + m];
            }
            vals[ni] = v;
        }
        if (OMODE == 0) {
            float4 r = make_float4(vals[0], vals[1], vals[2], vals[3]);
            *(float4*)&out[(size_t)m * N + n0 + tn * 4] = r;
        } else {
#pragma unroll
            for (int ni = 0; ni < 4; ni++)
                out[(size_t)(n0 + tn * 4 + ni) * HW + m] = vals[ni];
        }
    }
}

// ==================== tf32 tensor-core GEMM, cp.async 3-stage pipeline ====================
// Wm MUST be tf32-pre-rounded (g_wr) — B fragments are passed to mma without cvt.
template<int WM, int AMODE, int ACT, int OMODE>
__device__ __forceinline__ void tgemm_body(
    const float* __restrict__ A, const float* __restrict__ Wm,
    const float* __restrict__ bias, float* __restrict__ out,
    const float* __restrict__ extra, int K, int N)
{
    constexpr int BM = WM * 16, BN = 48, BK = 16;
    constexpr int PA = BM + 8, PB = 56;
    constexpr int NG = 8 / WM;
    constexpr int NMW = BN / (8 * NG);
    constexpr int LA = BM / 16;
    constexpr int LB = 3;
    __shared__ float sA[3][BK * PA];
    __shared__ float sB[3][BK * PB];
    int tid = threadIdx.x, lane = tid & 31, warp = tid >> 5;
    int gid = lane >> 2, tig = lane & 3;
    int pix0 = blockIdx.x * BM, n0 = blockIdx.y * BN;
    int warp_m = (warp % WM) * 16;
    int nwb = (warp / WM) * (BN / NG);

    float c[NMW][4];
#pragma unroll
    for (int i = 0; i < NMW; i++)
#pragma unroll
        for (int j = 0; j < 4; j++) c[i][j] = 0.f;

    int kchunks = (K + BK - 1) / BK;

    auto issue = [&](int kt) {
        int stage = kt % 3;
        uint32_t sa = (uint32_t)__cvta_generic_to_shared(&sA[stage][0]);
        uint32_t sb = (uint32_t)__cvta_generic_to_shared(&sB[stage][0]);
#pragma unroll
        for (int t = 0; t < LA; t++) {
            int idx = tid + t * 256;
            int kk, m;
            if (AMODE == 0) { kk = idx / BM; m = idx % BM; }
            else            { m = idx / BK; kk = idx % BK; }
            int i = kt * BK + kk;
            bool p = (i < K);
            int pix = pix0 + m;
            const float* g;
            if (AMODE == 0)      g = A + (size_t)i * HW + pix;
            else if (AMODE == 1) g = A + (size_t)pix * K + i;
            else                 g = A + (size_t)(pix * 12 + i / 24) * 32 + (i % 24);
            if (!p) g = A;
            cp_async4(sa + (uint32_t)(kk * PA + m) * 4u, g, p);
        }
#pragma unroll
        for (int t = 0; t < LB; t++) {
            int idx = tid + t * 256;
            int kk = idx / BN, n = idx - kk * BN;
            int i = kt * BK + kk;
            bool p = (i < K);
            const float* g = Wm + (size_t)i * N + n0 + n;
            if (!p) g = Wm;
            cp_async4(sb + (uint32_t)(kk * PB + n) * 4u, g, p);
        }
        cp_commit();
    };

    issue(0);
    if (kchunks > 1) issue(1); else cp_commit();

    for (int kt = 0; kt < kchunks; kt++) {
        cp_wait1();
        __syncthreads();
        if (kt + 2 < kchunks) issue(kt + 2); else cp_commit();
        const float* cA = &sA[kt % 3][0];
        const float* cB = &sB[kt % 3][0];
#pragma unroll
        for (int ks = 0; ks < 2; ks++) {
            int kb = ks * 8;
            unsigned a0 = cvt_tf32(cA[(kb + tig) * PA + warp_m + gid]);
            unsigned a1 = cvt_tf32(cA[(kb + tig) * PA + warp_m + gid + 8]);
            unsigned a2 = cvt_tf32(cA[(kb + tig + 4) * PA + warp_m + gid]);
            unsigned a3 = cvt_tf32(cA[(kb + tig + 4) * PA + warp_m + gid + 8]);
#pragma unroll
            for (int nm = 0; nm < NMW; nm++) {
                // B pre-rounded to tf32 in gmem: pass bits directly (cvt idempotent)
                unsigned b0 = __float_as_uint(cB[(kb + tig) * PB + nwb + nm * 8 + gid]);
                unsigned b1 = __float_as_uint(cB[(kb + tig + 4) * PB + nwb + nm * 8 + gid]);
                asm("mma.sync.aligned.m16n8k8.row.col.f32.tf32.tf32.f32 "
                    "{%0,%1,%2,%3}, {%4,%5,%6,%7}, {%8,%9}, {%0,%1,%2,%3};"
                    : "+f"(c[nm][0]), "+f"(c[nm][1]), "+f"(c[nm][2]), "+f"(c[nm][3])
                    : "r"(a0), "r"(a1), "r"(a2), "r"(a3), "r"(b0), "r"(b1));
            }
        }
        __syncthreads();
    }

#pragma unroll
    for (int nm = 0; nm < NMW; nm++) {
#pragma unroll
        for (int e = 0; e < 4; e++) {
            int m = pix0 + warp_m + gid + ((e >= 2) ? 8 : 0);
            int n = n0 + nwb + nm * 8 + 2 * tig + (e & 1);
            float v = c[nm][e] + bias[n];
            if (ACT == 2) {
                v = 0.5f * v * (1.f + erff(v * 0.70710678118654752f));
            } else if (ACT == 4) {
                v += extra[(size_t)m * N + n];
            }
            if (OMODE == 0)      out[(size_t)m * N + n] = v;
            else if (OMODE == 1) out[(size_t)n * HW + m] = v;
            else                 out[(size_t)(m * 12 + n / 24) * 32 + n % 24] = v;
        }
    }
}

template<int WM, int AMODE, int ACT, int OMODE>
__global__ void __launch_bounds__(256) tgemm_kernel(
    const float* __restrict__ A, const float* __restrict__ Wm,
    const float* __restrict__ bias, float* __restrict__ out,
    const float* __restrict__ extra, int K, int N)
{
    tgemm_body<WM, AMODE, ACT, OMODE>(A, Wm, bias, out, extra, K, N);
}

// batched q/k/v projection (grid.z dispatch), tf32, pre-rounded weights
__global__ void __launch_bounds__(256) gemm_proj_kernel(
    const float* __restrict__ q, const float* __restrict__ k,
    const float* __restrict__ v, const float* __restrict__ wr,
    const float* __restrict__ bq, const float* __restrict__ bk,
    const float* __restrict__ bv,
    float* __restrict__ qp, float* __restrict__ kp, float* __restrict__ vp)
{
    const float* A; const float* W; const float* b; float* o;
    switch (blockIdx.z) {
        case 0: A = q;            W = wr;           b = bq; o = qp;            break;
        case 1: A = k;            W = wr + WSZ;     b = bk; o = kp;            break;
        case 2: A = k + 144 * HW; W = wr + WSZ;     b = bk; o = kp + HW * 384; break;
        case 3: A = v;            W = wr + 2 * WSZ; b = bv; o = vp;            break;
        default:A = v + 144 * HW; W = wr + 2 * WSZ; b = bv; o = vp + HW * 384; break;
    }
    tgemm_body<8, 0, 0, 2>(A, W, b, o, nullptr, 144, 288);
}

// ---------------- 3x3 conv 64->64, pad 1, lrelu (fp32 exact; feeds offsets) ----------------
// R10-proven: OCB=4, CHB=4, 256 threads, grid (2, 8, 16) = 256 CTAs.
__global__ void __launch_bounds__(256) conv3x3_lrelu_kernel(
    const float* __restrict__ in, const float* __restrict__ w,
    const float* __restrict__ b, float* __restrict__ out)
{
    constexpr int OCB = 4, CHB = 4;
    __shared__ float s_h[2][CHB][10][34];
    __shared__ float s_w[OCB * 576];
    int tid = threadIdx.x;
    int tx = tid & 31, ty = tid >> 5;
    int x0 = blockIdx.x * 32, y0 = blockIdx.y * 8;
    int ocg = blockIdx.z * OCB;

    for (int i = tid; i < OCB * 576; i += 256) s_w[i] = w[ocg * 576 + i];

    auto loadH = [&](int icb, float r[6]) {
        const float* ip = in + (size_t)icb * CHB * HW;
#pragma unroll
        for (int t = 0; t < 6; t++) {
            int idx = tid + t * 256;
            float v = 0.f;
            if (idx < CHB * 340) {
                int icl = idx / 340, rem = idx - icl * 340;
                int hy = rem / 34, hx = rem - hy * 34;
                int gy = y0 + hy - 1, gx = x0 + hx - 1;
                if (gy >= 0 && gy < IMH && gx >= 0 && gx < IMW)
                    v = ip[(size_t)icl * HW + gy * IMW + gx];
            }
            r[t] = v;
        }
    };
    auto storeH = [&](int buf, float r[6]) {
#pragma unroll
        for (int t = 0; t < 6; t++) {
            int idx = tid + t * 256;
            if (idx < CHB * 340) {
                int icl = idx / 340, rem = idx - icl * 340;
                int hy = rem / 34, hx = rem - hy * 34;
                s_h[buf][icl][hy][hx] = r[t];
            }
        }
    };

    float acc[OCB];
#pragma unroll
    for (int o = 0; o < OCB; o++) acc[o] = b[ocg + o];

    float rcur[6];
    loadH(0, rcur);
    storeH(0, rcur);
    __syncthreads();

    int p = 0;
    for (int icb = 0; icb < 64 / CHB; icb++) {
        float rnext[6];
        if (icb + 1 < 64 / CHB) loadH(icb + 1, rnext);
#pragma unroll
        for (int icl = 0; icl < CHB; icl++) {
            int ic = icb * CHB + icl;
            float vv[9];
#pragma unroll
            for (int ky = 0; ky < 3; ky++)
#pragma unroll
                for (int kx = 0; kx < 3; kx++)
                    vv[ky * 3 + kx] = s_h[p][icl][ty + ky][tx + kx];
#pragma unroll
            for (int o = 0; o < OCB; o++) {
                const float* wp = &s_w[o * 576 + ic * 9];
#pragma unroll
                for (int kk = 0; kk < 9; kk++) acc[o] = fmaf(vv[kk], wp[kk], acc[o]);
            }
        }
        if (icb + 1 < 64 / CHB) {
            storeH(1 - p, rnext);
            __syncthreads();
            p ^= 1;
        }
    }

    int pix = (y0 + ty) * IMW + x0 + tx;
#pragma unroll
    for (int o = 0; o < OCB; o++) {
        float r = acc[o];
        out[(size_t)(ocg + o) * HW + pix] = r >= 0.f ? r : 0.1f * r;
    }
}

// ---------------- deformable attention, single pass, 2-sample ILP, fast exp ----------------
__global__ void __launch_bounds__(256) attn_kernel()
{
    int warp = threadIdx.x >> 5, lane = threadIdx.x & 31;
    int pix = blockIdx.x * 8 + warp;
    int m = blockIdx.y;
    int y = pix >> 6, x = pix & 63;

    float qv = g_qp[(size_t)pix * 384 + m * 32 + lane];

    const float* kb0 = g_kp + m * 32 + lane;
    const float* vb0 = g_vp + m * 32 + lane;
    const float* kb1 = kb0 + (size_t)HW * 384;
    const float* vb1 = vb0 + (size_t)HW * 384;

    float rmax = -1e30f, rsum = 0.f, racc = 0.f;

#pragma unroll
    for (int a = 0; a < 9; a++) {
        int och0 = (m * 9 + a) * 2;            // clip 0
        int och1 = ((12 + m) * 9 + a) * 2;     // clip 1
        float base_y = (float)(a / 3 - 1 + y);
        float base_x = (float)(a % 3 - 1 + x);
        float py0 = g_off[(size_t)och0 * HW + pix] + base_y;
        float px0 = g_off[(size_t)(och0 + 1) * HW + pix] + base_x;
        float py1 = g_off[(size_t)och1 * HW + pix] + base_y;
        float px1 = g_off[(size_t)(och1 + 1) * HW + pix] + base_x;

        float fy0 = floorf(py0), fx0 = floorf(px0);
        float fy1 = floorf(py1), fx1 = floorf(px1);
        int iy0 = (int)fy0, ix0 = (int)fx0;
        int iy1 = (int)fy1, ix1 = (int)fx1;
        float wy1a = py0 - fy0, wx1a = px0 - fx0;
        float wy1b = py1 - fy1, wx1b = px1 - fx1;
        float wy0a = 1.f - wy1a, wx0a = 1.f - wx1a;
        float wy0b = 1.f - wy1b, wx0b = 1.f - wx1b;

        float k0 = 0.f, v0 = 0.f, k1 = 0.f, v1 = 0.f;
#pragma unroll
        for (int cr = 0; cr < 4; cr++) {
            int dy = cr >> 1, dx = cr & 1;
            {
                int yy = iy0 + dy, xx = ix0 + dx;
                float wt = (dy ? wy1a : wy0a) * (dx ? wx1a : wx0a);
                if (yy >= 0 && yy < IMH && xx >= 0 && xx < IMW) {
                    size_t base = (size_t)(yy * IMW + xx) * 384;
                    k0 = fmaf(wt, kb0[base], k0);
                    v0 = fmaf(wt, vb0[base], v0);
                }
            }
            {
                int yy = iy1 + dy, xx = ix1 + dx;
                float wt = (dy ? wy1b : wy0b) * (dx ? wx1b : wx0b);
                if (yy >= 0 && yy < IMH && xx >= 0 && xx < IMW) {
                    size_t base = (size_t)(yy * IMW + xx) * 384;
                    k1 = fmaf(wt, kb1[base], k1);
                    v1 = fmaf(wt, vb1[base], v1);
                }
            }
        }

        float p0 = qv * k0;
        float p1 = qv * k1;
#pragma unroll
        for (int o = 16; o > 0; o >>= 1) {
            p0 += __shfl_xor_sync(0xffffffffu, p0, o);
            p1 += __shfl_xor_sync(0xffffffffu, p1, o);
        }
        float sc0 = p0 * 0.2041241452319315f;
        float sc1 = p1 * 0.2041241452319315f;

        // fused pairwise online-softmax update (fast MUFU exp)
        float mnew = fmaxf(rmax, fmaxf(sc0, sc1));
        float corr = __expf(rmax - mnew);
        float e0 = __expf(sc0 - mnew);
        float e1 = __expf(sc1 - mnew);
        rsum = rsum * corr + e0 + e1;
        racc = racc * corr + e0 * v0 + e1 * v1;
        rmax = mnew;
    }

    g_attnout[(size_t)pix * 384 + m * 32 + lane] = racc / rsum;
}

// ---------------- launcher ----------------
extern "C" void kernel_launch(void* const* d_in, const int* in_sizes, int n_in,
                              void* d_out, int out_size)
{
    const float* q     = (const float*)d_in[0];
    const float* k     = (const float*)d_in[1];
    const float* v     = (const float*)d_in[2];
    const float* vpw0  = (const float*)d_in[3];
    const float* vpw1  = (const float*)d_in[4];
    const float* flow0 = (const float*)d_in[5];
    const float* flow1 = (const float*)d_in[6];
    const float* wo1 = (const float*)d_in[7];  const float* bo1 = (const float*)d_in[8];
    const float* wo2 = (const float*)d_in[9];  const float* bo2 = (const float*)d_in[10];
    const float* wo3 = (const float*)d_in[11]; const float* bo3 = (const float*)d_in[12];
    const float* wo4 = (const float*)d_in[13]; const float* bo4 = (const float*)d_in[14];
    const float* wo5 = (const float*)d_in[15]; const float* bo5 = (const float*)d_in[16];
    const float* wo6 = (const float*)d_in[17]; const float* bo6 = (const float*)d_in[18];
    const float* wq  = (const float*)d_in[19]; const float* bq  = (const float*)d_in[20];
    const float* wk  = (const float*)d_in[21]; const float* bk  = (const float*)d_in[22];
    const float* wv  = (const float*)d_in[23]; const float* bv  = (const float*)d_in[24];
    const float* wp  = (const float*)d_in[25]; const float* bp  = (const float*)d_in[26];
    const float* wm1 = (const float*)d_in[27]; const float* bm1 = (const float*)d_in[28];
    const float* wm2 = (const float*)d_in[29]; const float* bm2 = (const float*)d_in[30];
    float* outp = (float*)d_out;
    (void)in_sizes; (void)n_in; (void)out_size; (void)flow1;

    float *p_w1t, *p_w6t, *p_wr, *p_b0, *p_b1, *p_off, *p_qp, *p_kp, *p_vp, *p_ao, *p_ob, *p_hb;
    cudaGetSymbolAddress((void**)&p_w1t, g_w1t);
    cudaGetSymbolAddress((void**)&p_w6t, g_w6t);
    cudaGetSymbolAddress((void**)&p_wr,  g_wr);
    cudaGetSymbolAddress((void**)&p_b0,  g_buf0);
    cudaGetSymbolAddress((void**)&p_b1,  g_buf1);
    cudaGetSymbolAddress((void**)&p_off, g_off);
    cudaGetSymbolAddress((void**)&p_qp,  g_qp);
    cudaGetSymbolAddress((void**)&p_kp,  g_kp);
    cudaGetSymbolAddress((void**)&p_vp,  g_vp);
    cudaGetSymbolAddress((void**)&p_ao,  g_attnout);
    cudaGetSymbolAddress((void**)&p_ob,  g_obuf);
    cudaGetSymbolAddress((void**)&p_hb,  g_hbuf);

    // 1: prep (transposes + tf32 weight rounding)   2: first 1x1 conv   3: proj
    int prep_elems = 436 * 64 + 432 * 64 + 6 * WSZ;
    prep_weights_kernel<<<(prep_elems + 255) / 256, 256>>>(wo1, wo6, wq, wk, wv, wp, wm1, wm2);
    gemm_kernel<32, 64, 32, 3, 1, 1><<<dim3(128, 1), 128>>>(q, p_w1t, bo1, p_b0, nullptr,
                                                            vpw0, vpw1, flow0, flow1, 436, 64);
    gemm_proj_kernel<<<dim3(32, 6, 5), 256>>>(q, k, v, p_wr, bq, bk, bv, p_qp, p_kp, p_vp);

    // 4 (profiled slot): conv#1
    conv3x3_lrelu_kernel<<<dim3(2, 8, 16), 256>>>(p_b0, wo2, bo2, p_b1);
    conv3x3_lrelu_kernel<<<dim3(2, 8, 16), 256>>>(p_b1, wo3, bo3, p_b0);
    conv3x3_lrelu_kernel<<<dim3(2, 8, 16), 256>>>(p_b0, wo4, bo4, p_b1);
    conv3x3_lrelu_kernel<<<dim3(2, 8, 16), 256>>>(p_b1, wo5, bo5, p_b0);
    gemm_kernel<64, 72, 32, 0, 3, 1><<<dim3(64, 6), 288>>>(p_b0, p_w6t, bo6, p_off, flow0,
                                                           nullptr, nullptr, nullptr, nullptr, 64, 432);

    // deformable attention (pairwise online-softmax, __expf)
    attn_kernel<<<dim3(512, 12), 256>>>();

    // output projection + MLP residual (tf32 + cp.async, pre-rounded weights)
    tgemm_kernel<4, 2, 0, 0><<<dim3(64, 3), 256>>>(p_ao, p_wr + 3 * WSZ, bp, p_ob, nullptr, 288, 144);
    tgemm_kernel<4, 1, 2, 0><<<dim3(64, 6), 256>>>(p_ob, p_wr + 4 * WSZ, bm1, p_hb, nullptr, 144, 288);
    tgemm_kernel<4, 1, 4, 1><<<dim3(64, 3), 256>>>(p_hb, p_wr + 5 * WSZ, bm2, outp, p_ob, 288, 144);
}

// round 16
// speedup vs baseline: 1.0804x; 1.0804x over previous
#include <cuda_runtime.h>
#include <math.h>
#include <stdint.h>

#define HW   4096
#define IMW  64
#define IMH  64

// ---------------- scratch (device globals; zero-initialized, no allocs) ----------------
__device__ __align__(16) float g_w1t[436 * 64];
__device__ __align__(16) float g_w6t[64 * 432];
__device__ __align__(16) float g_buf0[64 * HW];
__device__ __align__(16) float g_buf1[64 * HW];
__device__ __align__(16) float g_off[432 * HW];
// padded head layout: [pix][12 heads][32 ch] (24 real + 8 zero pad)
__device__ __align__(16) float g_qp[HW * 384];
__device__ __align__(16) float g_kp[2 * HW * 384];
__device__ __align__(16) float g_vp[2 * HW * 384];
__device__ __align__(16) float g_attnout[HW * 384];
__device__ __align__(16) float g_obuf[HW * 144];
__device__ __align__(16) float g_hbuf[HW * 288];

// ---------------- merged weight transposes (one launch) ----------------
__global__ void transpose_both_kernel(const float* __restrict__ w1,
                                      const float* __restrict__ w6)
{
    int idx = blockIdx.x * 256 + threadIdx.x;
    if (idx < 436 * 64) {
        int o = idx / 436, i = idx - o * 436;
        g_w1t[i * 64 + o] = w1[idx];
    } else {
        idx -= 436 * 64;
        if (idx < 432 * 64) {
            int o = idx / 64, i = idx - o * 64;
            g_w6t[i * 432 + o] = w6[idx];
        }
    }
}

// ---------------- cp.async helpers ----------------
__device__ __forceinline__ void cp_async4(uint32_t dst, const void* src, bool p) {
    int sz = p ? 4 : 0;
    asm volatile("cp.async.ca.shared.global [%0], [%1], 4, %2;\n"
                 :: "r"(dst), "l"(src), "r"(sz));
}
__device__ __forceinline__ void cp_commit() {
    asm volatile("cp.async.commit_group;\n");
}
__device__ __forceinline__ void cp_wait1() {
    asm volatile("cp.async.wait_group 1;\n");
}
__device__ __forceinline__ unsigned cvt_tf32(float x) {
    unsigned r;
    asm("cvt.rna.tf32.f32 %0, %1;" : "=r"(r) : "f"(x));
    return r;
}

// ==================== fp32 SGEMM (offset path only) ====================
template<int BM, int BN, int BK, int AMODE, int ACT, int OMODE>
__global__ void gemm_kernel(const float* __restrict__ A, const float* __restrict__ Wm,
                            const float* __restrict__ bias, float* __restrict__ out,
                            const float* __restrict__ extra,
                            const float* __restrict__ A2, const float* __restrict__ A3,
                            const float* __restrict__ A4, const float* __restrict__ A5,
                            int K, int N)
{
    constexpr int TH = BM * BN / 16;
    constexpr int TN = BN / 4;
    constexpr int LA = (BK * BM + TH - 1) / TH;
    constexpr int LW = (BK * BN + TH - 1) / TH;
    __shared__ __align__(16) float sA[BK][BM];
    __shared__ __align__(16) float sW[BK][BN];
    int tid = threadIdx.x;
    int tn = tid % TN, tm = tid / TN;
    int pix0 = blockIdx.x * BM;
    int n0 = blockIdx.y * BN;

    float acc[4][4];
#pragma unroll
    for (int i = 0; i < 4; i++)
#pragma unroll
        for (int j = 0; j < 4; j++) acc[i][j] = 0.f;

    float ra[LA], rw[LW];
    int ktiles = (K + BK - 1) / BK;

    auto loadA = [&](int kt) {
#pragma unroll
        for (int t = 0; t < LA; t++) {
            int idx = tid + t * TH;
            float v = 0.f;
            if (LA * TH == BK * BM || idx < BK * BM) {
                int kk = idx / BM, m = idx % BM;
                int i = kt * BK + kk;
                if (i < K) {
                    int pix = pix0 + m;
                    if (AMODE == 0) v = A[(size_t)i * HW + pix];
                    else {
                        if (i < 144)      v = A [(size_t)i * HW + pix];
                        else if (i < 288) v = A2[(size_t)(i - 144) * HW + pix];
                        else if (i < 432) v = A3[(size_t)(i - 288) * HW + pix];
                        else if (i < 434) v = A4[(size_t)(i - 432) * HW + pix];
                        else              v = A5[(size_t)(i - 434) * HW + pix];
                    }
                }
            }
            ra[t] = v;
        }
    };
    auto loadW = [&](int kt) {
#pragma unroll
        for (int t = 0; t < LW; t++) {
            int idx = tid + t * TH;
            float v = 0.f;
            if (LW * TH == BK * BN || idx < BK * BN) {
                int kk = idx / BN, n = idx - kk * BN;
                int i = kt * BK + kk;
                if (i < K) v = Wm[(size_t)i * N + n0 + n];
            }
            rw[t] = v;
        }
    };

    loadA(0); loadW(0);
    for (int kt = 0; kt < ktiles; kt++) {
#pragma unroll
        for (int t = 0; t < LA; t++) {
            int idx = tid + t * TH;
            if (LA * TH == BK * BM || idx < BK * BM) sA[idx / BM][idx % BM] = ra[t];
        }
#pragma unroll
        for (int t = 0; t < LW; t++) {
            int idx = tid + t * TH;
            if (LW * TH == BK * BN || idx < BK * BN) sW[idx / BN][idx - (idx / BN) * BN] = rw[t];
        }
        __syncthreads();
        if (kt + 1 < ktiles) { loadA(kt + 1); loadW(kt + 1); }
#pragma unroll
        for (int kk = 0; kk < BK; kk++) {
            float4 a4 = *(const float4*)&sA[kk][tm * 4];
            float4 w4 = *(const float4*)&sW[kk][tn * 4];
            float av[4] = {a4.x, a4.y, a4.z, a4.w};
            float wv[4] = {w4.x, w4.y, w4.z, w4.w};
#pragma unroll
            for (int i2 = 0; i2 < 4; i2++)
#pragma unroll
                for (int j = 0; j < 4; j++)
                    acc[i2][j] = fmaf(av[i2], wv[j], acc[i2][j]);
        }
        __syncthreads();
    }

#pragma unroll
    for (int mi = 0; mi < 4; mi++) {
        int m = pix0 + tm * 4 + mi;
        float vals[4];
#pragma unroll
        for (int ni = 0; ni < 4; ni++) {
            int n = n0 + tn * 4 + ni;
            float v = acc[mi][ni] + bias[n];
            if (ACT == 1) {
                v = v >= 0.f ? v : 0.1f * v;
            } else if (ACT == 3) {
                v = 10.f * tanhf(v);
                v += (n & 1) ? extra[m] : extra[HW + m];
            }
            vals[ni] = v;
        }
        if (OMODE == 0) {
            float4 r = make_float4(vals[0], vals[1], vals[2], vals[3]);
            *(float4*)&out[(size_t)m * N + n0 + tn * 4] = r;
        } else {
#pragma unroll
            for (int ni = 0; ni < 4; ni++)
                out[(size_t)(n0 + tn * 4 + ni) * HW + m] = vals[ni];
        }
    }
}

// ==================== tf32 tensor-core GEMM, cp.async 3-stage pipeline ====================
template<int WM, int AMODE, int ACT, int OMODE>
__device__ __forceinline__ void tgemm_body(
    const float* __restrict__ A, const float* __restrict__ Wm,
    const float* __restrict__ bias, float* __restrict__ out,
    const float* __restrict__ extra, int K, int N)
{
    constexpr int BM = WM * 16, BN = 48, BK = 16;
    constexpr int PA = BM + 8, PB = 56;
    constexpr int NG = 8 / WM;
    constexpr int NMW = BN / (8 * NG);
    constexpr int LA = BM / 16;
    constexpr int LB = 3;
    __shared__ float sA[3][BK * PA];
    __shared__ float sB[3][BK * PB];
    int tid = threadIdx.x, lane = tid & 31, warp = tid >> 5;
    int gid = lane >> 2, tig = lane & 3;
    int pix0 = blockIdx.x * BM, n0 = blockIdx.y * BN;
    int warp_m = (warp % WM) * 16;
    int nwb = (warp / WM) * (BN / NG);

    float c[NMW][4];
#pragma unroll
    for (int i = 0; i < NMW; i++)
#pragma unroll
        for (int j = 0; j < 4; j++) c[i][j] = 0.f;

    int kchunks = (K + BK - 1) / BK;

    auto issue = [&](int kt) {
        int stage = kt % 3;
        uint32_t sa = (uint32_t)__cvta_generic_to_shared(&sA[stage][0]);
        uint32_t sb = (uint32_t)__cvta_generic_to_shared(&sB[stage][0]);
#pragma unroll
        for (int t = 0; t < LA; t++) {
            int idx = tid + t * 256;
            int kk, m;
            if (AMODE == 0) { kk = idx / BM; m = idx % BM; }
            else            { m = idx / BK; kk = idx % BK; }
            int i = kt * BK + kk;
            bool p = (i < K);
            int pix = pix0 + m;
            const float* g;
            if (AMODE == 0)      g = A + (size_t)i * HW + pix;
            else if (AMODE == 1) g = A + (size_t)pix * K + i;
            else                 g = A + (size_t)(pix * 12 + i / 24) * 32 + (i % 24);
            if (!p) g = A;
            cp_async4(sa + (uint32_t)(kk * PA + m) * 4u, g, p);
        }
#pragma unroll
        for (int t = 0; t < LB; t++) {
            int idx = tid + t * 256;
            int kk = idx / BN, n = idx - kk * BN;
            int i = kt * BK + kk;
            bool p = (i < K);
            const float* g = Wm + (size_t)i * N + n0 + n;
            if (!p) g = Wm;
            cp_async4(sb + (uint32_t)(kk * PB + n) * 4u, g, p);
        }
        cp_commit();
    };

    issue(0);
    if (kchunks > 1) issue(1); else cp_commit();

    for (int kt = 0; kt < kchunks; kt++) {
        cp_wait1();
        __syncthreads();
        if (kt + 2 < kchunks) issue(kt + 2); else cp_commit();
        const float* cA = &sA[kt % 3][0];
        const float* cB = &sB[kt % 3][0];
#pragma unroll
        for (int ks = 0; ks < 2; ks++) {
            int kb = ks * 8;
            unsigned a0 = cvt_tf32(cA[(kb + tig) * PA + warp_m + gid]);
            unsigned a1 = cvt_tf32(cA[(kb + tig) * PA + warp_m + gid + 8]);
            unsigned a2 = cvt_tf32(cA[(kb + tig + 4) * PA + warp_m + gid]);
            unsigned a3 = cvt_tf32(cA[(kb + tig + 4) * PA + warp_m + gid + 8]);
#pragma unroll
            for (int nm = 0; nm < NMW; nm++) {
                unsigned b0 = cvt_tf32(cB[(kb + tig) * PB + nwb + nm * 8 + gid]);
                unsigned b1 = cvt_tf32(cB[(kb + tig + 4) * PB + nwb + nm * 8 + gid]);
                asm("mma.sync.aligned.m16n8k8.row.col.f32.tf32.tf32.f32 "
                    "{%0,%1,%2,%3}, {%4,%5,%6,%7}, {%8,%9}, {%0,%1,%2,%3};"
                    : "+f"(c[nm][0]), "+f"(c[nm][1]), "+f"(c[nm][2]), "+f"(c[nm][3])
                    : "r"(a0), "r"(a1), "r"(a2), "r"(a3), "r"(b0), "r"(b1));
            }
        }
        __syncthreads();
    }

#pragma unroll
    for (int nm = 0; nm < NMW; nm++) {
#pragma unroll
        for (int e = 0; e < 4; e++) {
            int m = pix0 + warp_m + gid + ((e >= 2) ? 8 : 0);
            int n = n0 + nwb + nm * 8 + 2 * tig + (e & 1);
            float v = c[nm][e] + bias[n];
            if (ACT == 2) {
                v = 0.5f * v * (1.f + erff(v * 0.70710678118654752f));
            } else if (ACT == 4) {
                v += extra[(size_t)m * N + n];
            }
            if (OMODE == 0)      out[(size_t)m * N + n] = v;
            else if (OMODE == 1) out[(size_t)n * HW + m] = v;
            else                 out[(size_t)(m * 12 + n / 24) * 32 + n % 24] = v;
        }
    }
}

template<int WM, int AMODE, int ACT, int OMODE>
__global__ void __launch_bounds__(256) tgemm_kernel(
    const float* __restrict__ A, const float* __restrict__ Wm,
    const float* __restrict__ bias, float* __restrict__ out,
    const float* __restrict__ extra, int K, int N)
{
    tgemm_body<WM, AMODE, ACT, OMODE>(A, Wm, bias, out, extra, K, N);
}

// batched q/k/v projection (grid.z dispatch), tf32
__global__ void __launch_bounds__(256) gemm_proj_kernel(
    const float* __restrict__ q, const float* __restrict__ k,
    const float* __restrict__ v,
    const float* __restrict__ wq, const float* __restrict__ bq,
    const float* __restrict__ wk, const float* __restrict__ bk,
    const float* __restrict__ wv, const float* __restrict__ bv,
    float* __restrict__ qp, float* __restrict__ kp, float* __restrict__ vp)
{
    const float* A; const float* W; const float* b; float* o;
    switch (blockIdx.z) {
        case 0: A = q;            W = wq; b = bq; o = qp;            break;
        case 1: A = k;            W = wk; b = bk; o = kp;            break;
        case 2: A = k + 144 * HW; W = wk; b = bk; o = kp + HW * 384; break;
        case 3: A = v;            W = wv; b = bv; o = vp;            break;
        default:A = v + 144 * HW; W = wv; b = bv; o = vp + HW * 384; break;
    }
    tgemm_body<8, 0, 0, 2>(A, W, b, o, nullptr, 144, 288);
}

// ---------------- 3x3 conv 64->64, pad 1, lrelu (fp32 exact; feeds offsets) ----------------
// WIDE CTA split-K: 512 threads, group 0 (warps 0-7) ic 0..31, group 1 (warps 8-15)
// ic 32..63, each with its own double-buffered halo; smem partial-sum combine at end.
// Per-warp work identical to R10 version; resident warps/SM 13.8 -> 27.7.
__global__ void __launch_bounds__(512) conv3x3_lrelu_kernel(
    const float* __restrict__ in, const float* __restrict__ w,
    const float* __restrict__ b, float* __restrict__ out)
{
    constexpr int OCB = 4, CHB = 4;
    __shared__ float s_h[2][2][CHB][10][34];   // [group][buf][ch][hy][hx]
    __shared__ float s_w[OCB * 576];
    __shared__ float s_red[OCB][256];
    int tid = threadIdx.x;
    int g = tid >> 8;                // 0 or 1
    int lt = tid & 255;
    int tx = lt & 31, ty = lt >> 5;
    int x0 = blockIdx.x * 32, y0 = blockIdx.y * 8;
    int ocg = blockIdx.z * OCB;

    for (int i = tid; i < OCB * 576; i += 512) s_w[i] = w[ocg * 576 + i];

    // halo loader for this group's channel block icb (4 channels x 10 x 34 = 1360)
    auto loadH = [&](int icb, float r[6]) {
        const float* ip = in + (size_t)(g * 32 + icb * CHB) * HW;
#pragma unroll
        for (int t = 0; t < 6; t++) {
            int idx = lt + t * 256;
            float v = 0.f;
            if (idx < CHB * 340) {
                int icl = idx / 340, rem = idx - icl * 340;
                int hy = rem / 34, hx = rem - hy * 34;
                int gy = y0 + hy - 1, gx = x0 + hx - 1;
                if (gy >= 0 && gy < IMH && gx >= 0 && gx < IMW)
                    v = ip[(size_t)icl * HW + gy * IMW + gx];
            }
            r[t] = v;
        }
    };
    auto storeH = [&](int buf, float r[6]) {
#pragma unroll
        for (int t = 0; t < 6; t++) {
            int idx = lt + t * 256;
            if (idx < CHB * 340) {
                int icl = idx / 340, rem = idx - icl * 340;
                int hy = rem / 34, hx = rem - hy * 34;
                s_h[g][buf][icl][hy][hx] = r[t];
            }
        }
    };

    float acc[OCB];
#pragma unroll
    for (int o = 0; o < OCB; o++) acc[o] = 0.f;

    float rcur[6];
    loadH(0, rcur);
    storeH(0, rcur);
    __syncthreads();

    int p = 0;
    for (int icb = 0; icb < 8; icb++) {          // 8 blocks of 4 channels per group
        float rnext[6];
        if (icb + 1 < 8) loadH(icb + 1, rnext);  // global prefetch overlaps compute
#pragma unroll
        for (int icl = 0; icl < CHB; icl++) {
            int ic = g * 32 + icb * CHB + icl;
            float vv[9];
#pragma unroll
            for (int ky = 0; ky < 3; ky++)
#pragma unroll
                for (int kx = 0; kx < 3; kx++)
                    vv[ky * 3 + kx] = s_h[g][p][icl][ty + ky][tx + kx];
#pragma unroll
            for (int o = 0; o < OCB; o++) {
                const float* wp = &s_w[o * 576 + ic * 9];
#pragma unroll
                for (int kk = 0; kk < 9; kk++) acc[o] = fmaf(vv[kk], wp[kk], acc[o]);
            }
        }
        if (icb + 1 < 8) {
            storeH(1 - p, rnext);
            __syncthreads();
            p ^= 1;
        }
    }

    // combine halves
    if (g == 1) {
#pragma unroll
        for (int o = 0; o < OCB; o++) s_red[o][lt] = acc[o];
    }
    __syncthreads();
    if (g == 0) {
        int pix = (y0 + ty) * IMW + x0 + tx;
#pragma unroll
        for (int o = 0; o < OCB; o++) {
            float r = acc[o] + s_red[o][lt] + b[ocg + o];
            out[(size_t)(ocg + o) * HW + pix] = r >= 0.f ? r : 0.1f * r;
        }
    }
}

// ---------------- deformable attention, single pass, 2-sample ILP, fast exp ----------------
__global__ void __launch_bounds__(256) attn_kernel()
{
    int warp = threadIdx.x >> 5, lane = threadIdx.x & 31;
    int pix = blockIdx.x * 8 + warp;
    int m = blockIdx.y;
    int y = pix >> 6, x = pix & 63;

    float qv = g_qp[(size_t)pix * 384 + m * 32 + lane];

    const float* kb0 = g_kp + m * 32 + lane;
    const float* vb0 = g_vp + m * 32 + lane;
    const float* kb1 = kb0 + (size_t)HW * 384;
    const float* vb1 = vb0 + (size_t)HW * 384;

    float rmax = -1e30f, rsum = 0.f, racc = 0.f;

#pragma unroll
    for (int a = 0; a < 9; a++) {
        int och0 = (m * 9 + a) * 2;            // clip 0
        int och1 = ((12 + m) * 9 + a) * 2;     // clip 1
        float base_y = (float)(a / 3 - 1 + y);
        float base_x = (float)(a % 3 - 1 + x);
        float py0 = g_off[(size_t)och0 * HW + pix] + base_y;
        float px0 = g_off[(size_t)(och0 + 1) * HW + pix] + base_x;
        float py1 = g_off[(size_t)och1 * HW + pix] + base_y;
        float px1 = g_off[(size_t)(och1 + 1) * HW + pix] + base_x;

        float fy0 = floorf(py0), fx0 = floorf(px0);
        float fy1 = floorf(py1), fx1 = floorf(px1);
        int iy0 = (int)fy0, ix0 = (int)fx0;
        int iy1 = (int)fy1, ix1 = (int)fx1;
        float wy1a = py0 - fy0, wx1a = px0 - fx0;
        float wy1b = py1 - fy1, wx1b = px1 - fx1;
        float wy0a = 1.f - wy1a, wx0a = 1.f - wx1a;
        float wy0b = 1.f - wy1b, wx0b = 1.f - wx1b;

        float k0 = 0.f, v0 = 0.f, k1 = 0.f, v1 = 0.f;
#pragma unroll
        for (int cr = 0; cr < 4; cr++) {
            int dy = cr >> 1, dx = cr & 1;
            {
                int yy = iy0 + dy, xx = ix0 + dx;
                float wt = (dy ? wy1a : wy0a) * (dx ? wx1a : wx0a);
                if (yy >= 0 && yy < IMH && xx >= 0 && xx < IMW) {
                    size_t base = (size_t)(yy * IMW + xx) * 384;
                    k0 = fmaf(wt, kb0[base], k0);
                    v0 = fmaf(wt, vb0[base], v0);
                }
            }
            {
                int yy = iy1 + dy, xx = ix1 + dx;
                float wt = (dy ? wy1b : wy0b) * (dx ? wx1b : wx0b);
                if (yy >= 0 && yy < IMH && xx >= 0 && xx < IMW) {
                    size_t base = (size_t)(yy * IMW + xx) * 384;
                    k1 = fmaf(wt, kb1[base], k1);
                    v1 = fmaf(wt, vb1[base], v1);
                }
            }
        }

        float p0 = qv * k0;
        float p1 = qv * k1;
#pragma unroll
        for (int o = 16; o > 0; o >>= 1) {
            p0 += __shfl_xor_sync(0xffffffffu, p0, o);
            p1 += __shfl_xor_sync(0xffffffffu, p1, o);
        }
        float sc0 = p0 * 0.2041241452319315f;
        float sc1 = p1 * 0.2041241452319315f;

        float mnew = fmaxf(rmax, fmaxf(sc0, sc1));
        float corr = __expf(rmax - mnew);
        float e0 = __expf(sc0 - mnew);
        float e1 = __expf(sc1 - mnew);
        rsum = rsum * corr + e0 + e1;
        racc = racc * corr + e0 * v0 + e1 * v1;
        rmax = mnew;
    }

    g_attnout[(size_t)pix * 384 + m * 32 + lane] = racc / rsum;
}

// ---------------- launcher ----------------
extern "C" void kernel_launch(void* const* d_in, const int* in_sizes, int n_in,
                              void* d_out, int out_size)
{
    const float* q     = (const float*)d_in[0];
    const float* k     = (const float*)d_in[1];
    const float* v     = (const float*)d_in[2];
    const float* vpw0  = (const float*)d_in[3];
    const float* vpw1  = (const float*)d_in[4];
    const float* flow0 = (const float*)d_in[5];
    const float* flow1 = (const float*)d_in[6];
    const float* wo1 = (const float*)d_in[7];  const float* bo1 = (const float*)d_in[8];
    const float* wo2 = (const float*)d_in[9];  const float* bo2 = (const float*)d_in[10];
    const float* wo3 = (const float*)d_in[11]; const float* bo3 = (const float*)d_in[12];
    const float* wo4 = (const float*)d_in[13]; const float* bo4 = (const float*)d_in[14];
    const float* wo5 = (const float*)d_in[15]; const float* bo5 = (const float*)d_in[16];
    const float* wo6 = (const float*)d_in[17]; const float* bo6 = (const float*)d_in[18];
    const float* wq  = (const float*)d_in[19]; const float* bq  = (const float*)d_in[20];
    const float* wk  = (const float*)d_in[21]; const float* bk  = (const float*)d_in[22];
    const float* wv  = (const float*)d_in[23]; const float* bv  = (const float*)d_in[24];
    const float* wp  = (const float*)d_in[25]; const float* bp  = (const float*)d_in[26];
    const float* wm1 = (const float*)d_in[27]; const float* bm1 = (const float*)d_in[28];
    const float* wm2 = (const float*)d_in[29]; const float* bm2 = (const float*)d_in[30];
    float* outp = (float*)d_out;
    (void)in_sizes; (void)n_in; (void)out_size; (void)flow1;

    float *p_w1t, *p_w6t, *p_b0, *p_b1, *p_off, *p_qp, *p_kp, *p_vp, *p_ao, *p_ob, *p_hb;
    cudaGetSymbolAddress((void**)&p_w1t, g_w1t);
    cudaGetSymbolAddress((void**)&p_w6t, g_w6t);
    cudaGetSymbolAddress((void**)&p_b0,  g_buf0);
    cudaGetSymbolAddress((void**)&p_b1,  g_buf1);
    cudaGetSymbolAddress((void**)&p_off, g_off);
    cudaGetSymbolAddress((void**)&p_qp,  g_qp);
    cudaGetSymbolAddress((void**)&p_kp,  g_kp);
    cudaGetSymbolAddress((void**)&p_vp,  g_vp);
    cudaGetSymbolAddress((void**)&p_ao,  g_attnout);
    cudaGetSymbolAddress((void**)&p_ob,  g_obuf);
    cudaGetSymbolAddress((void**)&p_hb,  g_hbuf);

    // 1: merged transposes   2: first 1x1 conv (concat fused)   3: proj
    transpose_both_kernel<<<(436 * 64 + 432 * 64 + 255) / 256, 256>>>(wo1, wo6);
    gemm_kernel<32, 64, 32, 3, 1, 1><<<dim3(128, 1), 128>>>(q, p_w1t, bo1, p_b0, nullptr,
                                                            vpw0, vpw1, flow0, flow1, 436, 64);
    gemm_proj_kernel<<<dim3(32, 6, 5), 256>>>(q, k, v, wq, bq, wk, bk, wv, bv, p_qp, p_kp, p_vp);

    // 4 (profiled slot): conv#1 — wide-CTA split-K version (512 threads)
    conv3x3_lrelu_kernel<<<dim3(2, 8, 16), 512>>>(p_b0, wo2, bo2, p_b1);
    conv3x3_lrelu_kernel<<<dim3(2, 8, 16), 512>>>(p_b1, wo3, bo3, p_b0);
    conv3x3_lrelu_kernel<<<dim3(2, 8, 16), 512>>>(p_b0, wo4, bo4, p_b1);
    conv3x3_lrelu_kernel<<<dim3(2, 8, 16), 512>>>(p_b1, wo5, bo5, p_b0);
    gemm_kernel<64, 72, 32, 0, 3, 1><<<dim3(64, 6), 288>>>(p_b0, p_w6t, bo6, p_off, flow0,
                                                           nullptr, nullptr, nullptr, nullptr, 64, 432);

    // deformable attention (pairwise online-softmax, __expf)
    attn_kernel<<<dim3(512, 12), 256>>>();

    // output projection + MLP residual (tf32 + cp.async)
    tgemm_kernel<4, 2, 0, 0><<<dim3(64, 3), 256>>>(p_ao, wp, bp, p_ob, nullptr, 288, 144);
    tgemm_kernel<4, 1, 2, 0><<<dim3(64, 6), 256>>>(p_ob, wm1, bm1, p_hb, nullptr, 144, 288);
    tgemm_kernel<4, 1, 4, 1><<<dim3(64, 3), 256>>>(p_hb, wm2, bm2, outp, p_ob, 288, 144);
}